// round 1
// baseline (speedup 1.0000x reference)
#include <cuda_runtime.h>
#include <cuda_fp16.h>

#define HH 512
#define WW 512
#define CC 128
#define NPTS 524288
#define PLANE_ELEMS (CC * HH * WW)

// Transposed fp16 planes: layout [H][W][C] (channel-last, contiguous per texel).
// __device__ globals are the sanctioned scratch (no cudaMalloc allowed).
__device__ __align__(16) __half g_uvT[PLANE_ELEMS];
__device__ __align__(16) __half g_stT[PLANE_ELEMS];

// ---------------------------------------------------------------------------
// Kernel 1: transpose [C,H,W] fp32 -> [H,W,C] fp16, shared-mem tiled.
// grid: (W/32, H, 2 planes), block: (32, 8)
// ---------------------------------------------------------------------------
__global__ __launch_bounds__(256) void transpose_kernel(
    const float* __restrict__ uv, const float* __restrict__ st) {
    __shared__ float tile[CC][33];  // pad to 33 to kill bank conflicts

    const float* src = (blockIdx.z == 0) ? uv : st;
    __half* dst = (blockIdx.z == 0) ? g_uvT : g_stT;

    const int y = blockIdx.y;
    const int x0 = blockIdx.x * 32;
    const int tx = threadIdx.x;  // 0..31 (x within tile)
    const int ty = threadIdx.y;  // 0..7

    // Load: lanes sweep x (coalesced 128B per row), loop over channels.
    #pragma unroll
    for (int i = 0; i < 16; i++) {
        const int c = ty + i * 8;
        tile[c][tx] = src[c * (HH * WW) + y * WW + x0 + tx];
    }
    __syncthreads();

    // Store: lanes sweep c (contiguous fp16 per texel), loop over x in tile.
    const int t = ty * 32 + tx;
    const int c = t & 127;
    const int xb = t >> 7;  // 0 or 1
    #pragma unroll
    for (int i = 0; i < 16; i++) {
        const int xi = xb + i * 2;
        dst[(y * WW + x0 + xi) * CC + c] = __float2half_rn(tile[c][xi]);
    }
}

// ---------------------------------------------------------------------------
// Kernel 2: warp-per-point bilinear gather + product + comp-sum + sigmoid.
// ---------------------------------------------------------------------------
__device__ __forceinline__ void sample_corners(
    const __half* __restrict__ T, int y0, int x0, float wx, float wy, int ch,
    float v[4]) {
    const int base = (y0 * WW + x0) * CC + ch;

    // 4 corners, each: one 8-byte load = 4 fp16 channels.
    const uint2 r00 = *(const uint2*)(T + base);
    const uint2 r01 = *(const uint2*)(T + base + CC);
    const uint2 r10 = *(const uint2*)(T + base + WW * CC);
    const uint2 r11 = *(const uint2*)(T + base + WW * CC + CC);

    const float w00 = (1.f - wx) * (1.f - wy);
    const float w01 = wx * (1.f - wy);
    const float w10 = (1.f - wx) * wy;
    const float w11 = wx * wy;

    float2 a, b, c, d;
    a = __half22float2(*(const __half2*)&r00.x);
    b = __half22float2(*(const __half2*)&r01.x);
    c = __half22float2(*(const __half2*)&r10.x);
    d = __half22float2(*(const __half2*)&r11.x);
    v[0] = a.x * w00 + b.x * w01 + c.x * w10 + d.x * w11;
    v[1] = a.y * w00 + b.y * w01 + c.y * w10 + d.y * w11;
    a = __half22float2(*(const __half2*)&r00.y);
    b = __half22float2(*(const __half2*)&r01.y);
    c = __half22float2(*(const __half2*)&r10.y);
    d = __half22float2(*(const __half2*)&r11.y);
    v[2] = a.x * w00 + b.x * w01 + c.x * w10 + d.x * w11;
    v[3] = a.y * w00 + b.y * w01 + c.y * w10 + d.y * w11;
}

__global__ __launch_bounds__(256) void point_kernel(
    const float4* __restrict__ xs, const float* __restrict__ bounds,
    float* __restrict__ out) {
    const int gw = (blockIdx.x * 256 + threadIdx.x) >> 5;  // global warp = point
    const int lane = threadIdx.x & 31;
    if (gw >= NPTS) return;

    const float4 p = xs[gw];

    // ix = ((x-b0)/(b1-b0)*2-1 + 1)*0.5*(W-1) = (x-b0)/(b1-b0)*(W-1)
    const float ixu = (p.x - bounds[0]) / (bounds[4] - bounds[0]) * (WW - 1);
    const float iyu = (p.y - bounds[1]) / (bounds[5] - bounds[1]) * (HH - 1);
    const float ixs = (p.z - bounds[2]) / (bounds[6] - bounds[2]) * (WW - 1);
    const float iys = (p.w - bounds[3]) / (bounds[7] - bounds[3]) * (HH - 1);

    const int xu0 = min(max(__float2int_rd(ixu), 0), WW - 2);
    const int yu0 = min(max(__float2int_rd(iyu), 0), HH - 2);
    const int xs0 = min(max(__float2int_rd(ixs), 0), WW - 2);
    const int ys0 = min(max(__float2int_rd(iys), 0), HH - 2);

    const float wxu = ixu - (float)xu0, wyu = iyu - (float)yu0;
    const float wxs = ixs - (float)xs0, wys = iys - (float)ys0;

    const int ch = lane * 4;  // this lane's 4 channels

    float uvv[4], stv[4];
    sample_corners(g_uvT, yu0, xu0, wxu, wyu, ch, uvv);
    sample_corners(g_stT, ys0, xs0, wxs, wys, ch, stv);

    float r[4];
    #pragma unroll
    for (int j = 0; j < 4; j++) r[j] = uvv[j] * stv[j];

    // channel c = 4*lane + j -> output (c % 8). Even lanes hold outs 0..3,
    // odd lanes hold outs 4..7. Butterfly over even strides sums the 16
    // same-parity lanes (i.e. sums over the 16 components).
    #pragma unroll
    for (int s = 16; s >= 2; s >>= 1) {
        #pragma unroll
        for (int j = 0; j < 4; j++)
            r[j] += __shfl_xor_sync(0xffffffffu, r[j], s);
    }

    if (lane < 2) {
        float4 o;
        o.x = 1.f / (1.f + expf(-r[0]));
        o.y = 1.f / (1.f + expf(-r[1]));
        o.z = 1.f / (1.f + expf(-r[2]));
        o.w = 1.f / (1.f + expf(-r[3]));
        ((float4*)out)[gw * 2 + lane] = o;  // lane0: outs 0..3, lane1: outs 4..7
    }
}

// ---------------------------------------------------------------------------
extern "C" void kernel_launch(void* const* d_in, const int* in_sizes, int n_in,
                              void* d_out, int out_size) {
    const float* x = (const float*)d_in[0];
    const float* uv = (const float*)d_in[1];
    const float* st = (const float*)d_in[2];
    const float* bounds = (const float*)d_in[3];
    float* out = (float*)d_out;

    dim3 tb(32, 8);
    dim3 tg(WW / 32, HH, 2);
    transpose_kernel<<<tg, tb>>>(uv, st);

    const int nblocks = (NPTS * 32) / 256;  // warp per point, 8 warps/block
    point_kernel<<<nblocks, 256>>>((const float4*)x, bounds, out);
}

// round 2
// speedup vs baseline: 1.1813x; 1.1813x over previous
#include <cuda_runtime.h>
#include <cuda_fp16.h>

#define HH 512
#define WW 512
#define CC 128
#define NPTS 524288
#define PLANE_ELEMS (CC * HH * WW)

// Transposed fp16 planes [H][W][C] + per-point precomputed params.
__device__ __align__(16) __half g_uvT[PLANE_ELEMS];
__device__ __align__(16) __half g_stT[PLANE_ELEMS];
__device__ __align__(16) uint4 g_params[NPTS * 3];  // {bases, uv weights, st weights}

// ---------------------------------------------------------------------------
// Kernel 1: transpose [C,H,W] fp32 -> [H,W,C] fp16, shared-mem tiled.
// grid: (W/32, H, 2), block: (32, 8)
// ---------------------------------------------------------------------------
__global__ __launch_bounds__(256) void transpose_kernel(
    const float* __restrict__ uv, const float* __restrict__ st) {
    __shared__ float tile[CC][33];

    const float* src = (blockIdx.z == 0) ? uv : st;
    __half* dst = (blockIdx.z == 0) ? g_uvT : g_stT;

    const int y = blockIdx.y;
    const int x0 = blockIdx.x * 32;
    const int tx = threadIdx.x;
    const int ty = threadIdx.y;

    #pragma unroll
    for (int i = 0; i < 16; i++) {
        const int c = ty + i * 8;
        tile[c][tx] = src[c * (HH * WW) + y * WW + x0 + tx];
    }
    __syncthreads();

    // Each thread writes half2 (2 consecutive channels): warp = 128B full line.
    const int t = ty * 32 + tx;
    const int c2 = (t & 63) * 2;
    const int xb = t >> 6;  // 0..3
    #pragma unroll
    for (int i = 0; i < 8; i++) {
        const int xi = xb + i * 4;
        __half2 v = __floats2half2_rn(tile[c2][xi], tile[c2 + 1][xi]);
        *(__half2*)(dst + (size_t)(y * WW + x0 + xi) * CC + c2) = v;
    }
}

// ---------------------------------------------------------------------------
// Kernel 2: per-point setup — bases + bilinear weights (as dup'd half2).
// ---------------------------------------------------------------------------
__device__ __forceinline__ unsigned packw(float w) {
    __half2 h = __float2half2_rn(w);
    return *(unsigned*)&h;
}

__global__ __launch_bounds__(256) void setup_kernel(
    const float4* __restrict__ xs, const float* __restrict__ b) {
    const int i = blockIdx.x * 256 + threadIdx.x;
    const float4 p = xs[i];

    const float ixu = __fdividef(p.x - b[0], b[4] - b[0]) * (WW - 1);
    const float iyu = __fdividef(p.y - b[1], b[5] - b[1]) * (HH - 1);
    const float ixs = __fdividef(p.z - b[2], b[6] - b[2]) * (WW - 1);
    const float iys = __fdividef(p.w - b[3], b[7] - b[3]) * (HH - 1);

    const int xu0 = min(max(__float2int_rd(ixu), 0), WW - 2);
    const int yu0 = min(max(__float2int_rd(iyu), 0), HH - 2);
    const int xs0 = min(max(__float2int_rd(ixs), 0), WW - 2);
    const int ys0 = min(max(__float2int_rd(iys), 0), HH - 2);

    const float wxu = ixu - (float)xu0, wyu = iyu - (float)yu0;
    const float wxs = ixs - (float)xs0, wys = iys - (float)ys0;

    uint4 A;
    A.x = (unsigned)((yu0 * WW + xu0) * CC);
    A.y = (unsigned)((ys0 * WW + xs0) * CC);
    A.z = 0; A.w = 0;

    uint4 WU;
    WU.x = packw((1.f - wxu) * (1.f - wyu));
    WU.y = packw(wxu * (1.f - wyu));
    WU.z = packw((1.f - wxu) * wyu);
    WU.w = packw(wxu * wyu);

    uint4 WS;
    WS.x = packw((1.f - wxs) * (1.f - wys));
    WS.y = packw(wxs * (1.f - wys));
    WS.z = packw((1.f - wxs) * wys);
    WS.w = packw(wxs * wys);

    g_params[3 * i] = A;
    g_params[3 * i + 1] = WU;
    g_params[3 * i + 2] = WS;
}

// ---------------------------------------------------------------------------
// Kernel 3: 16 lanes per point; lane = 8 channels via one uint4 per corner.
// ---------------------------------------------------------------------------
__device__ __forceinline__ __half2 u2h(unsigned u) { return *(__half2*)&u; }

__global__ __launch_bounds__(256) void point_kernel(float* __restrict__ out) {
    const int warp = (blockIdx.x * 256 + threadIdx.x) >> 5;
    const int lane = threadIdx.x & 31;
    const int sub = lane >> 4;   // which point within the warp
    const int gl = lane & 15;    // lane within 16-lane group
    const int p = warp * 2 + sub;

    const uint4 A  = g_params[3 * p];
    const uint4 WU = g_params[3 * p + 1];
    const uint4 WS = g_params[3 * p + 2];

    const __half* U = g_uvT + A.x + gl * 8;
    const __half* S = g_stT + A.y + gl * 8;

    // 8 independent 16B loads (MLP=8).
    const uint4 u00 = *(const uint4*)(U);
    const uint4 u01 = *(const uint4*)(U + CC);
    const uint4 u10 = *(const uint4*)(U + WW * CC);
    const uint4 u11 = *(const uint4*)(U + WW * CC + CC);
    const uint4 s00 = *(const uint4*)(S);
    const uint4 s01 = *(const uint4*)(S + CC);
    const uint4 s10 = *(const uint4*)(S + WW * CC);
    const uint4 s11 = *(const uint4*)(S + WW * CC + CC);

    __half2 au[4], av[4];
    {
        const __half2 w00 = u2h(WU.x), w01 = u2h(WU.y), w10 = u2h(WU.z), w11 = u2h(WU.w);
        const __half2* p00 = (const __half2*)&u00;
        const __half2* p01 = (const __half2*)&u01;
        const __half2* p10 = (const __half2*)&u10;
        const __half2* p11 = (const __half2*)&u11;
        #pragma unroll
        for (int j = 0; j < 4; j++) {
            __half2 a = __hmul2(p00[j], w00);
            a = __hfma2(p01[j], w01, a);
            a = __hfma2(p10[j], w10, a);
            au[j] = __hfma2(p11[j], w11, a);
        }
    }
    {
        const __half2 w00 = u2h(WS.x), w01 = u2h(WS.y), w10 = u2h(WS.z), w11 = u2h(WS.w);
        const __half2* p00 = (const __half2*)&s00;
        const __half2* p01 = (const __half2*)&s01;
        const __half2* p10 = (const __half2*)&s10;
        const __half2* p11 = (const __half2*)&s11;
        #pragma unroll
        for (int j = 0; j < 4; j++) {
            __half2 a = __hmul2(p00[j], w00);
            a = __hfma2(p01[j], w01, a);
            a = __hfma2(p10[j], w10, a);
            av[j] = __hfma2(p11[j], w11, a);
        }
    }

    // Product, convert to f32. f[k] = partial for output k (k = c mod 8).
    float f[8];
    #pragma unroll
    for (int j = 0; j < 4; j++) {
        const float2 t = __half22float2(__hmul2(au[j], av[j]));
        f[2 * j] = t.x;
        f[2 * j + 1] = t.y;
    }

    // Sum over the 16 lanes of the group (16 components).
    #pragma unroll
    for (int s = 8; s >= 1; s >>= 1) {
        #pragma unroll
        for (int j = 0; j < 8; j++)
            f[j] += __shfl_xor_sync(0xffffffffu, f[j], s);
    }

    if (gl == 0) {
        float4 o0, o1;
        o0.x = 1.f / (1.f + __expf(-f[0]));
        o0.y = 1.f / (1.f + __expf(-f[1]));
        o0.z = 1.f / (1.f + __expf(-f[2]));
        o0.w = 1.f / (1.f + __expf(-f[3]));
        o1.x = 1.f / (1.f + __expf(-f[4]));
        o1.y = 1.f / (1.f + __expf(-f[5]));
        o1.z = 1.f / (1.f + __expf(-f[6]));
        o1.w = 1.f / (1.f + __expf(-f[7]));
        ((float4*)out)[p * 2] = o0;
        ((float4*)out)[p * 2 + 1] = o1;
    }
}

// ---------------------------------------------------------------------------
extern "C" void kernel_launch(void* const* d_in, const int* in_sizes, int n_in,
                              void* d_out, int out_size) {
    const float* x = (const float*)d_in[0];
    const float* uv = (const float*)d_in[1];
    const float* st = (const float*)d_in[2];
    const float* bounds = (const float*)d_in[3];
    float* out = (float*)d_out;

    setup_kernel<<<NPTS / 256, 256>>>((const float4*)x, bounds);

    dim3 tb(32, 8);
    dim3 tg(WW / 32, HH, 2);
    transpose_kernel<<<tg, tb>>>(uv, st);

    // 2 points per warp, 8 warps per block -> 16 points/block.
    point_kernel<<<NPTS / 16, 256>>>(out);
}

// round 3
// speedup vs baseline: 1.2121x; 1.0262x over previous
#include <cuda_runtime.h>
#include <cuda_fp16.h>

#define HH 512
#define WW 512
#define CC 128
#define NPTS 524288
#define PLANE_ELEMS (CC * HH * WW)

#define TRANS_BLOCKS (2 * HH * (WW / 32))  // 16384
#define SETUP_BLOCKS (NPTS / 256)          // 2048

// Transposed fp16 planes [H][W][C] + per-point precomputed params.
__device__ __align__(16) __half g_uvT[PLANE_ELEMS];
__device__ __align__(16) __half g_stT[PLANE_ELEMS];
__device__ __align__(16) uint4 g_params[NPTS * 3];  // {bases, uv weights, st weights}

__device__ __forceinline__ unsigned packw(float w) {
    __half2 h = __float2half2_rn(w);
    return *(unsigned*)&h;
}

// ---------------------------------------------------------------------------
// Kernel 1 (fused): transpose [C,H,W] f32 -> [H,W,C] f16  +  per-point setup.
// 1-D grid: blocks [0, TRANS_BLOCKS) transpose, rest do setup.
// Transpose is DRAM-bound, setup is latency-bound -> they overlap cleanly.
// ---------------------------------------------------------------------------
__global__ __launch_bounds__(256) void prep_kernel(
    const float* __restrict__ uv, const float* __restrict__ st,
    const float4* __restrict__ xs, const float* __restrict__ b) {
    const int bid = blockIdx.x;
    const int tid = threadIdx.x;

    if (bid < TRANS_BLOCKS) {
        // ---- transpose path ----
        __shared__ float tile[CC][33];
        const int plane = bid >> 13;             // /8192
        const int rem = bid & 8191;
        const int y = rem >> 4;
        const int x0 = (rem & 15) * 32;
        const int tx = tid & 31;
        const int ty = tid >> 5;

        const float* src = plane ? st : uv;
        __half* dst = plane ? g_stT : g_uvT;

        #pragma unroll
        for (int i = 0; i < 16; i++) {
            const int c = ty + i * 8;
            tile[c][tx] = src[c * (HH * WW) + y * WW + x0 + tx];
        }
        __syncthreads();

        const int c2 = (tid & 63) * 2;
        const int xb = tid >> 6;  // 0..3
        #pragma unroll
        for (int i = 0; i < 8; i++) {
            const int xi = xb + i * 4;
            __half2 v = __floats2half2_rn(tile[c2][xi], tile[c2 + 1][xi]);
            *(__half2*)(dst + (size_t)(y * WW + x0 + xi) * CC + c2) = v;
        }
    } else {
        // ---- setup path ----
        const int i = (bid - TRANS_BLOCKS) * 256 + tid;
        const float4 p = xs[i];

        const float ixu = __fdividef(p.x - b[0], b[4] - b[0]) * (WW - 1);
        const float iyu = __fdividef(p.y - b[1], b[5] - b[1]) * (HH - 1);
        const float ixs = __fdividef(p.z - b[2], b[6] - b[2]) * (WW - 1);
        const float iys = __fdividef(p.w - b[3], b[7] - b[3]) * (HH - 1);

        const int xu0 = min(max(__float2int_rd(ixu), 0), WW - 2);
        const int yu0 = min(max(__float2int_rd(iyu), 0), HH - 2);
        const int xs0 = min(max(__float2int_rd(ixs), 0), WW - 2);
        const int ys0 = min(max(__float2int_rd(iys), 0), HH - 2);

        const float wxu = ixu - (float)xu0, wyu = iyu - (float)yu0;
        const float wxs = ixs - (float)xs0, wys = iys - (float)ys0;

        uint4 A;
        A.x = (unsigned)((yu0 * WW + xu0) * CC);
        A.y = (unsigned)((ys0 * WW + xs0) * CC);
        A.z = 0; A.w = 0;

        uint4 WU;
        WU.x = packw((1.f - wxu) * (1.f - wyu));
        WU.y = packw(wxu * (1.f - wyu));
        WU.z = packw((1.f - wxu) * wyu);
        WU.w = packw(wxu * wyu);

        uint4 WS;
        WS.x = packw((1.f - wxs) * (1.f - wys));
        WS.y = packw(wxs * (1.f - wys));
        WS.z = packw((1.f - wxs) * wys);
        WS.w = packw(wxs * wys);

        g_params[3 * i] = A;
        g_params[3 * i + 1] = WU;
        g_params[3 * i + 2] = WS;
    }
}

// ---------------------------------------------------------------------------
// Kernel 2: 16 lanes per point; lane = 8 channels via one uint4 per corner.
// Params read with evict-first, output stored streaming -> planes keep L2.
// ---------------------------------------------------------------------------
__device__ __forceinline__ __half2 u2h(unsigned u) { return *(__half2*)&u; }

__global__ __launch_bounds__(256) void point_kernel(float* __restrict__ out) {
    const int warp = (blockIdx.x * 256 + threadIdx.x) >> 5;
    const int lane = threadIdx.x & 31;
    const int sub = lane >> 4;
    const int gl = lane & 15;
    const int p = warp * 2 + sub;

    const uint4 A  = __ldcs(&g_params[3 * p]);
    const uint4 WU = __ldcs(&g_params[3 * p + 1]);
    const uint4 WS = __ldcs(&g_params[3 * p + 2]);

    const __half* U = g_uvT + A.x + gl * 8;
    const __half* S = g_stT + A.y + gl * 8;

    const uint4 u00 = *(const uint4*)(U);
    const uint4 u01 = *(const uint4*)(U + CC);
    const uint4 u10 = *(const uint4*)(U + WW * CC);
    const uint4 u11 = *(const uint4*)(U + WW * CC + CC);
    const uint4 s00 = *(const uint4*)(S);
    const uint4 s01 = *(const uint4*)(S + CC);
    const uint4 s10 = *(const uint4*)(S + WW * CC);
    const uint4 s11 = *(const uint4*)(S + WW * CC + CC);

    __half2 au[4], av[4];
    {
        const __half2 w00 = u2h(WU.x), w01 = u2h(WU.y), w10 = u2h(WU.z), w11 = u2h(WU.w);
        const __half2* p00 = (const __half2*)&u00;
        const __half2* p01 = (const __half2*)&u01;
        const __half2* p10 = (const __half2*)&u10;
        const __half2* p11 = (const __half2*)&u11;
        #pragma unroll
        for (int j = 0; j < 4; j++) {
            __half2 a = __hmul2(p00[j], w00);
            a = __hfma2(p01[j], w01, a);
            a = __hfma2(p10[j], w10, a);
            au[j] = __hfma2(p11[j], w11, a);
        }
    }
    {
        const __half2 w00 = u2h(WS.x), w01 = u2h(WS.y), w10 = u2h(WS.z), w11 = u2h(WS.w);
        const __half2* p00 = (const __half2*)&s00;
        const __half2* p01 = (const __half2*)&s01;
        const __half2* p10 = (const __half2*)&s10;
        const __half2* p11 = (const __half2*)&s11;
        #pragma unroll
        for (int j = 0; j < 4; j++) {
            __half2 a = __hmul2(p00[j], w00);
            a = __hfma2(p01[j], w01, a);
            a = __hfma2(p10[j], w10, a);
            av[j] = __hfma2(p11[j], w11, a);
        }
    }

    float f[8];
    #pragma unroll
    for (int j = 0; j < 4; j++) {
        const float2 t = __half22float2(__hmul2(au[j], av[j]));
        f[2 * j] = t.x;
        f[2 * j + 1] = t.y;
    }

    #pragma unroll
    for (int s = 8; s >= 1; s >>= 1) {
        #pragma unroll
        for (int j = 0; j < 8; j++)
            f[j] += __shfl_xor_sync(0xffffffffu, f[j], s);
    }

    if (gl == 0) {
        float4 o0, o1;
        o0.x = 1.f / (1.f + __expf(-f[0]));
        o0.y = 1.f / (1.f + __expf(-f[1]));
        o0.z = 1.f / (1.f + __expf(-f[2]));
        o0.w = 1.f / (1.f + __expf(-f[3]));
        o1.x = 1.f / (1.f + __expf(-f[4]));
        o1.y = 1.f / (1.f + __expf(-f[5]));
        o1.z = 1.f / (1.f + __expf(-f[6]));
        o1.w = 1.f / (1.f + __expf(-f[7]));
        __stcs(&((float4*)out)[p * 2], o0);
        __stcs(&((float4*)out)[p * 2 + 1], o1);
    }
}

// ---------------------------------------------------------------------------
extern "C" void kernel_launch(void* const* d_in, const int* in_sizes, int n_in,
                              void* d_out, int out_size) {
    const float* x = (const float*)d_in[0];
    const float* uv = (const float*)d_in[1];
    const float* st = (const float*)d_in[2];
    const float* bounds = (const float*)d_in[3];
    float* out = (float*)d_out;

    prep_kernel<<<TRANS_BLOCKS + SETUP_BLOCKS, 256>>>(
        uv, st, (const float4*)x, bounds);

    point_kernel<<<NPTS / 16, 256>>>(out);
}